// round 2
// baseline (speedup 1.0000x reference)
#include <cuda_runtime.h>

#define DEV_INLINE __device__ __forceinline__

// Problem constants
constexpr int BATCH = 32;
constexpr int SEQ   = 1024;
constexpr int HD    = 256;
constexpr int MTOT  = BATCH * SEQ;   // 32768

// GEMM tiling
constexpr int BM = 128, BN = 128, BK = 16;
constexpr int NTST = 20;    // padded smem stride for NT tiles ([row][k-permuted])
constexpr int NNST = 132;   // padded smem stride for NN B tiles ([k][n])
constexpr int TILE_WORDS = BM * NTST;  // 2560 floats

// ---------------------------------------------------------------------------
// Scratch (device globals: the sanctioned no-alloc path)
// ---------------------------------------------------------------------------
__device__ float g_Q [(size_t)MTOT * HD];
__device__ float g_K [(size_t)MTOT * HD];
__device__ float g_V [(size_t)MTOT * HD];
__device__ float g_O [(size_t)MTOT * HD];
__device__ float g_X1[(size_t)MTOT * HD];
__device__ float g_T1[(size_t)MTOT * HD];
__device__ float g_T2[(size_t)MTOT * HD];
__device__ float g_F [(size_t)MTOT * HD];
__device__ float g_S [(size_t)BATCH * SEQ * SEQ];   // 128 MB: exp(scores)
__device__ float g_P [(size_t)BATCH * 8 * SEQ];     // per n-tile partial row sums
__device__ float g_Ri[(size_t)BATCH * SEQ];         // 1 / rowsum

// ---------------------------------------------------------------------------
// Helpers
// ---------------------------------------------------------------------------
DEV_INLINE float to_tf32(float x) {
    unsigned u;
    asm("cvt.rna.tf32.f32 %0, %1;" : "=r"(u) : "f"(x));
    return __uint_as_float(u);
}

DEV_INLINE unsigned f2b(float x) { return __float_as_uint(x); }

DEV_INLINE void mma_tf32(float c[4], const unsigned a[4], const unsigned b[2]) {
    asm volatile(
        "mma.sync.aligned.m16n8k8.row.col.f32.tf32.tf32.f32 "
        "{%0,%1,%2,%3}, {%4,%5,%6,%7}, {%8,%9}, {%0,%1,%2,%3};"
        : "+f"(c[0]), "+f"(c[1]), "+f"(c[2]), "+f"(c[3])
        : "r"(a[0]), "r"(a[1]), "r"(a[2]), "r"(a[3]), "r"(b[0]), "r"(b[1]));
}

DEV_INLINE float wsum(float v) {
    #pragma unroll
    for (int o = 16; o; o >>= 1) v += __shfl_xor_sync(0xffffffffu, v, o);
    return v;
}

// ---------------------------------------------------------------------------
// Generic tf32 GEMM: C[M,N] = A[M,K] @ B' (+ epilogue)
//   BNT=true : B is [N,K] row-major (NT — weights, QK^T)
//   BNT=false: B is [K,N] row-major (NN — P@V)
//   EPI: 0 = +bias[col]
//        1 = scores: store exp(scale*s + bias'), emit per-row partial sums
//        3 = scale rows by aux (1/rowsum)
// NT smem tiles use a k-permutation so mma fragment pairs (k, k+4) are
// contiguous -> LDS.64 fragment loads.
//   phys slot within 8-group: (k&3)*2 + ((k>>2)&1); groups of 8 keep base.
// ---------------------------------------------------------------------------
template<int EPI, bool BNT>
__global__ void __launch_bounds__(256) gemm_k(
    const float* __restrict__ Ag, const float* __restrict__ Bg,
    const float* __restrict__ aux, float* __restrict__ Cg,
    int Kdim, int ldA, int ldB, int ldC,
    size_t sA, size_t sB, size_t sC, int auxStride,
    float* __restrict__ Ppart)
{
    __shared__ float sA2[2][TILE_WORDS];
    __shared__ float sB2[2][TILE_WORDS];

    const int z = blockIdx.z;
    const float* A    = Ag  + (size_t)z * sA;
    const float* B    = Bg  + (size_t)z * sB;
    float*       C    = Cg  + (size_t)z * sC;
    const float* auxp = aux + (size_t)z * auxStride;

    const int m0 = blockIdx.y * BM;
    const int n0 = blockIdx.x * BN;
    const int tid  = threadIdx.x;
    const int warp = tid >> 5, lane = tid & 31;
    const int wm = warp >> 1, wn = warp & 1;
    const int gr = lane >> 2, tig = lane & 3;

    float acc[2][8][4];
    #pragma unroll
    for (int t = 0; t < 2; t++)
        #pragma unroll
        for (int j = 0; j < 8; j++)
            #pragma unroll
            for (int q = 0; q < 4; q++) acc[t][j][q] = 0.f;

    const int ar  = tid >> 2;           // 0..63 (row for NT tiles)
    const int ac  = (tid & 3) * 4;      // logical k base: 0,4,8,12
    // permuted physical base for the 4 consecutive logical ks this thread stages
    const int pbase = (ac & 8) + ((ac & 4) >> 2);   // 0,1,8,9 ; element i -> +2*i
    const int bkr = tid >> 5;           // 0..7  (k row for NN tiles)
    const int bnc = (tid & 31) * 4;     // 0..124

    float4 ra[2], rb[2];

    auto stage = [&](int buf) {
        {
            float* pa0 = &sA2[buf][ar * NTST + pbase];
            pa0[0]=to_tf32(ra[0].x); pa0[2]=to_tf32(ra[0].y); pa0[4]=to_tf32(ra[0].z); pa0[6]=to_tf32(ra[0].w);
            float* pa1 = &sA2[buf][(ar + 64) * NTST + pbase];
            pa1[0]=to_tf32(ra[1].x); pa1[2]=to_tf32(ra[1].y); pa1[4]=to_tf32(ra[1].z); pa1[6]=to_tf32(ra[1].w);
        }
        if (BNT) {
            float* pb0 = &sB2[buf][ar * NTST + pbase];
            pb0[0]=to_tf32(rb[0].x); pb0[2]=to_tf32(rb[0].y); pb0[4]=to_tf32(rb[0].z); pb0[6]=to_tf32(rb[0].w);
            float* pb1 = &sB2[buf][(ar + 64) * NTST + pbase];
            pb1[0]=to_tf32(rb[1].x); pb1[2]=to_tf32(rb[1].y); pb1[4]=to_tf32(rb[1].z); pb1[6]=to_tf32(rb[1].w);
        } else {
            float* pb0 = &sB2[buf][bkr * NNST + bnc];
            pb0[0]=to_tf32(rb[0].x); pb0[1]=to_tf32(rb[0].y); pb0[2]=to_tf32(rb[0].z); pb0[3]=to_tf32(rb[0].w);
            float* pb1 = &sB2[buf][(bkr + 8) * NNST + bnc];
            pb1[0]=to_tf32(rb[1].x); pb1[1]=to_tf32(rb[1].y); pb1[2]=to_tf32(rb[1].z); pb1[3]=to_tf32(rb[1].w);
        }
    };

    auto gload = [&](int k0) {
        const float* ap = A + (size_t)(m0 + ar) * ldA + k0 + ac;
        ra[0] = *(const float4*)ap;
        ra[1] = *(const float4*)(ap + (size_t)64 * ldA);
        if (BNT) {
            const float* bp = B + (size_t)(n0 + ar) * ldB + k0 + ac;
            rb[0] = *(const float4*)bp;
            rb[1] = *(const float4*)(bp + (size_t)64 * ldB);
        } else {
            const float* bp = B + (size_t)(k0 + bkr) * ldB + n0 + bnc;
            rb[0] = *(const float4*)bp;
            rb[1] = *(const float4*)(bp + (size_t)8 * ldB);
        }
    };

    gload(0);
    stage(0);
    __syncthreads();

    const int KB = Kdim / BK;
    for (int kt = 0; kt < KB; kt++) {
        const int cur = kt & 1;
        const bool more = (kt + 1 < KB);
        if (more) gload((kt + 1) * BK);

        #pragma unroll
        for (int kk = 0; kk < 2; kk++) {
            unsigned af[2][4];
            #pragma unroll
            for (int t = 0; t < 2; t++) {
                const int r = wm * 32 + t * 16 + gr;
                const float2 p0 = *(const float2*)&sA2[cur][r * NTST + kk * 8 + 2 * tig];
                const float2 p1 = *(const float2*)&sA2[cur][(r + 8) * NTST + kk * 8 + 2 * tig];
                af[t][0] = f2b(p0.x);
                af[t][1] = f2b(p1.x);
                af[t][2] = f2b(p0.y);
                af[t][3] = f2b(p1.y);
            }
            #pragma unroll
            for (int j = 0; j < 8; j++) {
                unsigned bf[2];
                if (BNT) {
                    const float2 pb = *(const float2*)&sB2[cur][(wn * 64 + j * 8 + gr) * NTST + kk * 8 + 2 * tig];
                    bf[0] = f2b(pb.x);
                    bf[1] = f2b(pb.y);
                } else {
                    const float* pb = &sB2[cur][(kk * 8 + tig) * NNST + wn * 64 + j * 8 + gr];
                    bf[0] = f2b(pb[0]);
                    bf[1] = f2b(pb[4 * NNST]);
                }
                #pragma unroll
                for (int t = 0; t < 2; t++) mma_tf32(acc[t][j], af[t], bf);
            }
        }

        if (more) stage(cur ^ 1);
        __syncthreads();
    }

    // Epilogue
    const float SCALE = 0.0625f;  // 1/sqrt(256)
    float rs[2][2];
    rs[0][0] = rs[0][1] = rs[1][0] = rs[1][1] = 0.f;

    #pragma unroll
    for (int t = 0; t < 2; t++) {
        const int r0 = m0 + wm * 32 + t * 16 + gr;
        const int r1 = r0 + 8;
        float mq0 = 0.f, mq1 = 0.f;
        if (EPI == 1) { mq0 = auxp[r0]; mq1 = auxp[r1]; }
        float rv0 = 0.f, rv1 = 0.f;
        if (EPI == 3) { rv0 = auxp[r0]; rv1 = auxp[r1]; }
        #pragma unroll
        for (int j = 0; j < 8; j++) {
            const int c = n0 + wn * 64 + j * 8 + 2 * tig;
            float x0 = acc[t][j][0], x1 = acc[t][j][1];
            float x2 = acc[t][j][2], x3 = acc[t][j][3];
            if (EPI == 0) {
                const float b0 = auxp[c], b1 = auxp[c + 1];
                float2 v0 = {x0 + b0, x1 + b1};
                float2 v1 = {x2 + b0, x3 + b1};
                *(float2*)&C[(size_t)r0 * ldC + c] = v0;
                *(float2*)&C[(size_t)r1 * ldC + c] = v1;
            } else if (EPI == 1) {
                // shift-invariant mask bias: mq ? (mk ? 1 : -1e5) : 0,
                // then exp without max-subtraction (row max is O(1) by design)
                const float mc0 = auxp[c], mc1 = auxp[c + 1];
                float e00, e01, e10, e11;
                if (mq0 > 0.5f) {
                    e00 = (mc0 > 0.5f) ? __expf(x0 * SCALE + 1.f) : 0.f;
                    e01 = (mc1 > 0.5f) ? __expf(x1 * SCALE + 1.f) : 0.f;
                } else {
                    e00 = __expf(x0 * SCALE);
                    e01 = __expf(x1 * SCALE);
                }
                if (mq1 > 0.5f) {
                    e10 = (mc0 > 0.5f) ? __expf(x2 * SCALE + 1.f) : 0.f;
                    e11 = (mc1 > 0.5f) ? __expf(x3 * SCALE + 1.f) : 0.f;
                } else {
                    e10 = __expf(x2 * SCALE);
                    e11 = __expf(x3 * SCALE);
                }
                rs[t][0] += e00 + e01;
                rs[t][1] += e10 + e11;
                float2 v0 = {e00, e01};
                float2 v1 = {e10, e11};
                *(float2*)&C[(size_t)r0 * ldC + c] = v0;
                *(float2*)&C[(size_t)r1 * ldC + c] = v1;
            } else {
                float2 v0 = {x0 * rv0, x1 * rv0};
                float2 v1 = {x2 * rv1, x3 * rv1};
                *(float2*)&C[(size_t)r0 * ldC + c] = v0;
                *(float2*)&C[(size_t)r1 * ldC + c] = v1;
            }
        }
    }

    if (EPI == 1) {
        // deterministic partial row-sum reduction: quad shuffle -> smem ->
        // cross-warp (wn) add -> global partial buffer [z][ntile][row]
        float* part = &sA2[0][0];   // reuse smem (all warps are past last sync'd read)
        #pragma unroll
        for (int t = 0; t < 2; t++) {
            #pragma unroll
            for (int rr = 0; rr < 2; rr++) {
                float v = rs[t][rr];
                v += __shfl_xor_sync(0xffffffffu, v, 1);
                v += __shfl_xor_sync(0xffffffffu, v, 2);
                if (tig == 0)
                    part[wn * 128 + wm * 32 + t * 16 + rr * 8 + gr] = v;
            }
        }
        __syncthreads();
        if (tid < 128) {
            const float l = part[tid] + part[128 + tid];
            Ppart[((size_t)z * 8 + blockIdx.x) * SEQ + m0 + tid] = l;
        }
    }
}

// ---------------------------------------------------------------------------
// Combine per-tile partial sums into 1/rowsum. One thread per row.
// ---------------------------------------------------------------------------
__global__ void __launch_bounds__(256) rinv_k(const float* __restrict__ P,
                                             float* __restrict__ R)
{
    const int i = blockIdx.x * 256 + threadIdx.x;   // 0 .. 32*1024-1
    const int z = i >> 10, row = i & 1023;
    float l = 0.f;
    #pragma unroll
    for (int nt = 0; nt < 8; nt++)
        l += P[(((size_t)z * 8 + nt) << 10) + row];
    R[i] = 1.f / l;
}

// ---------------------------------------------------------------------------
// Y = relu(LN(X)) rowwise over H=256. One warp per row, 8 rows per block.
// ---------------------------------------------------------------------------
__global__ void __launch_bounds__(256) relu_ln_k(
    const float* __restrict__ X, const float* __restrict__ G,
    const float* __restrict__ Bt, float* __restrict__ Y)
{
    const int row  = blockIdx.x * 8 + (threadIdx.x >> 5);
    const int lane = threadIdx.x & 31;
    const float4* x4 = reinterpret_cast<const float4*>(X + (size_t)row * HD);
    float4 a = x4[lane], b = x4[lane + 32];

    float s = a.x + a.y + a.z + a.w + b.x + b.y + b.z + b.w;
    s = wsum(s);
    const float mu = s * (1.f / HD);
    a.x -= mu; a.y -= mu; a.z -= mu; a.w -= mu;
    b.x -= mu; b.y -= mu; b.z -= mu; b.w -= mu;
    float q = a.x*a.x + a.y*a.y + a.z*a.z + a.w*a.w
            + b.x*b.x + b.y*b.y + b.z*b.z + b.w*b.w;
    q = wsum(q);
    const float inv = rsqrtf(q * (1.f / HD) + 1e-5f);

    const float4* g4 = reinterpret_cast<const float4*>(G);
    const float4* c4 = reinterpret_cast<const float4*>(Bt);
    float4 g0 = g4[lane], g1 = g4[lane + 32];
    float4 c0 = c4[lane], c1 = c4[lane + 32];

    float4 o0, o1;
    o0.x = fmaxf(a.x * inv * g0.x + c0.x, 0.f);
    o0.y = fmaxf(a.y * inv * g0.y + c0.y, 0.f);
    o0.z = fmaxf(a.z * inv * g0.z + c0.z, 0.f);
    o0.w = fmaxf(a.w * inv * g0.w + c0.w, 0.f);
    o1.x = fmaxf(b.x * inv * g1.x + c1.x, 0.f);
    o1.y = fmaxf(b.y * inv * g1.y + c1.y, 0.f);
    o1.z = fmaxf(b.z * inv * g1.z + c1.z, 0.f);
    o1.w = fmaxf(b.w * inv * g1.w + c1.w, 0.f);

    float4* y4 = reinterpret_cast<float4*>(Y + (size_t)row * HD);
    y4[lane] = o0; y4[lane + 32] = o1;
}

// ---------------------------------------------------------------------------
// Y = LN(Xa;Ga,Ba) + LN(Xb;Gb,Bb), optional relu. One warp per row.
// ---------------------------------------------------------------------------
__global__ void __launch_bounds__(256) dual_ln_add_k(
    const float* __restrict__ Xa, const float* __restrict__ Xb,
    const float* __restrict__ Ga, const float* __restrict__ Ba,
    const float* __restrict__ Gb, const float* __restrict__ Bb,
    float* __restrict__ Y, int doRelu)
{
    const int row  = blockIdx.x * 8 + (threadIdx.x >> 5);
    const int lane = threadIdx.x & 31;

    const float4* xa4 = reinterpret_cast<const float4*>(Xa + (size_t)row * HD);
    const float4* xb4 = reinterpret_cast<const float4*>(Xb + (size_t)row * HD);
    float4 a0 = xa4[lane], a1 = xa4[lane + 32];
    float4 b0 = xb4[lane], b1 = xb4[lane + 32];

    float sa = a0.x+a0.y+a0.z+a0.w + a1.x+a1.y+a1.z+a1.w;
    float sb = b0.x+b0.y+b0.z+b0.w + b1.x+b1.y+b1.z+b1.w;
    sa = wsum(sa); sb = wsum(sb);
    const float mua = sa * (1.f / HD), mub = sb * (1.f / HD);
    a0.x-=mua; a0.y-=mua; a0.z-=mua; a0.w-=mua;
    a1.x-=mua; a1.y-=mua; a1.z-=mua; a1.w-=mua;
    b0.x-=mub; b0.y-=mub; b0.z-=mub; b0.w-=mub;
    b1.x-=mub; b1.y-=mub; b1.z-=mub; b1.w-=mub;
    float qa = a0.x*a0.x+a0.y*a0.y+a0.z*a0.z+a0.w*a0.w
             + a1.x*a1.x+a1.y*a1.y+a1.z*a1.z+a1.w*a1.w;
    float qb = b0.x*b0.x+b0.y*b0.y+b0.z*b0.z+b0.w*b0.w
             + b1.x*b1.x+b1.y*b1.y+b1.z*b1.z+b1.w*b1.w;
    qa = wsum(qa); qb = wsum(qb);
    const float inva = rsqrtf(qa * (1.f / HD) + 1e-5f);
    const float invb = rsqrtf(qb * (1.f / HD) + 1e-5f);

    const float4* ga4 = reinterpret_cast<const float4*>(Ga);
    const float4* ba4 = reinterpret_cast<const float4*>(Ba);
    const float4* gb4 = reinterpret_cast<const float4*>(Gb);
    const float4* bb4 = reinterpret_cast<const float4*>(Bb);
    float4 ga0 = ga4[lane], ga1 = ga4[lane + 32];
    float4 ca0 = ba4[lane], ca1 = ba4[lane + 32];
    float4 gb0 = gb4[lane], gb1 = gb4[lane + 32];
    float4 cb0 = bb4[lane], cb1 = bb4[lane + 32];

    float4 o0, o1;
    o0.x = (a0.x*inva*ga0.x + ca0.x) + (b0.x*invb*gb0.x + cb0.x);
    o0.y = (a0.y*inva*ga0.y + ca0.y) + (b0.y*invb*gb0.y + cb0.y);
    o0.z = (a0.z*inva*ga0.z + ca0.z) + (b0.z*invb*gb0.z + cb0.z);
    o0.w = (a0.w*inva*ga0.w + ca0.w) + (b0.w*invb*gb0.w + cb0.w);
    o1.x = (a1.x*inva*ga1.x + ca1.x) + (b1.x*invb*gb1.x + cb1.x);
    o1.y = (a1.y*inva*ga1.y + ca1.y) + (b1.y*invb*gb1.y + cb1.y);
    o1.z = (a1.z*inva*ga1.z + ca1.z) + (b1.z*invb*gb1.z + cb1.z);
    o1.w = (a1.w*inva*ga1.w + ca1.w) + (b1.w*invb*gb1.w + cb1.w);
    if (doRelu) {
        o0.x = fmaxf(o0.x, 0.f); o0.y = fmaxf(o0.y, 0.f);
        o0.z = fmaxf(o0.z, 0.f); o0.w = fmaxf(o0.w, 0.f);
        o1.x = fmaxf(o1.x, 0.f); o1.y = fmaxf(o1.y, 0.f);
        o1.z = fmaxf(o1.z, 0.f); o1.w = fmaxf(o1.w, 0.f);
    }

    float4* y4 = reinterpret_cast<float4*>(Y + (size_t)row * HD);
    y4[lane] = o0; y4[lane + 32] = o1;
}

// ---------------------------------------------------------------------------
// Host launch
// ---------------------------------------------------------------------------
extern "C" void kernel_launch(void* const* d_in, const int* in_sizes, int n_in,
                              void* d_out, int out_size)
{
    (void)in_sizes; (void)n_in; (void)out_size;
    const float* feats   = (const float*)d_in[0];
    const float* masks   = (const float*)d_in[1];
    const float* qw      = (const float*)d_in[2];
    const float* qbias   = (const float*)d_in[3];
    const float* kw      = (const float*)d_in[4];
    const float* kbias   = (const float*)d_in[5];
    const float* vw      = (const float*)d_in[6];
    const float* vbias   = (const float*)d_in[7];
    const float* alng    = (const float*)d_in[8];
    const float* alnb    = (const float*)d_in[9];
    const float* caw     = (const float*)d_in[10];
    const float* cabias  = (const float*)d_in[11];
    const float* calng   = (const float*)d_in[12];
    const float* calnb   = (const float*)d_in[13];
    const float* lw      = (const float*)d_in[14];
    const float* lbias   = (const float*)d_in[15];
    const float* llng    = (const float*)d_in[16];
    const float* llnb    = (const float*)d_in[17];
    float* out = (float*)d_out;

    float *Q, *K, *V, *O, *X1, *T1, *T2, *F, *S, *P, *Ri;
    cudaGetSymbolAddress((void**)&Q,  g_Q);
    cudaGetSymbolAddress((void**)&K,  g_K);
    cudaGetSymbolAddress((void**)&V,  g_V);
    cudaGetSymbolAddress((void**)&O,  g_O);
    cudaGetSymbolAddress((void**)&X1, g_X1);
    cudaGetSymbolAddress((void**)&T1, g_T1);
    cudaGetSymbolAddress((void**)&T2, g_T2);
    cudaGetSymbolAddress((void**)&F,  g_F);
    cudaGetSymbolAddress((void**)&S,  g_S);
    cudaGetSymbolAddress((void**)&P,  g_P);
    cudaGetSymbolAddress((void**)&Ri, g_Ri);

    const dim3 blk(256);
    const dim3 gProj(HD / BN, MTOT / BM, 1);          // (2, 256)
    const dim3 gScore(SEQ / BN, SEQ / BM, BATCH);     // (8, 8, 32)
    const dim3 gPV(HD / BN, SEQ / BM, BATCH);         // (2, 8, 32)

    for (int i = 0; i < 3; i++) {
        const float* Fin = (i == 0) ? feats : F;
        const size_t wOff = (size_t)i * HD * HD;
        const size_t bOff = (size_t)i * HD;

        gemm_k<0, true><<<gProj, blk>>>(Fin, qw + wOff, qbias + bOff, Q,
                                        HD, HD, HD, HD, 0, 0, 0, 0, nullptr);
        gemm_k<0, true><<<gProj, blk>>>(Fin, kw + wOff, kbias + bOff, K,
                                        HD, HD, HD, HD, 0, 0, 0, 0, nullptr);
        gemm_k<0, true><<<gProj, blk>>>(Fin, vw + wOff, vbias + bOff, V,
                                        HD, HD, HD, HD, 0, 0, 0, 0, nullptr);

        // scores: writes exp(scaled scores + shift-invariant bias), emits
        // per n-tile partial row sums into P
        gemm_k<1, true><<<gScore, blk>>>(Q, K, masks, S,
                                         HD, HD, HD, SEQ,
                                         (size_t)SEQ * HD, (size_t)SEQ * HD,
                                         (size_t)SEQ * SEQ, SEQ, P);

        rinv_k<<<MTOT / 256, blk>>>(P, Ri);

        // PV: rows scaled by 1/rowsum in epilogue
        gemm_k<3, false><<<gPV, blk>>>(S, V, Ri, O,
                                       SEQ, SEQ, HD, HD,
                                       (size_t)SEQ * SEQ, (size_t)SEQ * HD,
                                       (size_t)SEQ * HD, SEQ, nullptr);

        relu_ln_k<<<MTOT / 8, blk>>>(O, alng + bOff, alnb + bOff, X1);

        gemm_k<0, true><<<gProj, blk>>>(X1, caw + wOff, cabias + bOff, T1,
                                        HD, HD, HD, HD, 0, 0, 0, 0, nullptr);
        gemm_k<0, true><<<gProj, blk>>>(Fin, lw + wOff, lbias + bOff, T2,
                                        HD, HD, HD, HD, 0, 0, 0, 0, nullptr);

        dual_ln_add_k<<<MTOT / 8, blk>>>(T1, T2,
                                         calng + bOff, calnb + bOff,
                                         llng + bOff, llnb + bOff,
                                         (i == 2) ? out : F, (i < 2) ? 1 : 0);
    }
}

// round 4
// speedup vs baseline: 1.2131x; 1.2131x over previous
#include <cuda_runtime.h>
#include <cstdint>

#define DEV_INLINE __device__ __forceinline__

// Problem constants
constexpr int BATCH = 32;
constexpr int SEQ   = 1024;
constexpr int HD    = 256;
constexpr int MTOT  = BATCH * SEQ;   // 32768

// GEMM tiling (all GEMMs are NT: C[M,N] = A[M,K] @ B[N,K]^T, K-major operands)
constexpr int BM = 128, BN = 128, BK = 16;
constexpr int ST = 20;                   // padded smem row stride (floats)
constexpr int TILE_WORDS = BM * ST;      // 2560 floats per tile

// ---------------------------------------------------------------------------
// Scratch (device globals: the sanctioned no-alloc path)
// ---------------------------------------------------------------------------
__device__ float g_Q [(size_t)MTOT * HD];
__device__ float g_K [(size_t)MTOT * HD];
__device__ float g_V [(size_t)MTOT * HD];
__device__ float g_VT[(size_t)MTOT * HD];           // per-batch transposed V
__device__ float g_O [(size_t)MTOT * HD];
__device__ float g_X1[(size_t)MTOT * HD];
__device__ float g_T1[(size_t)MTOT * HD];
__device__ float g_T2[(size_t)MTOT * HD];
__device__ float g_F [(size_t)MTOT * HD];
__device__ float g_S [(size_t)BATCH * SEQ * SEQ];   // 128 MB: exp(scores)
__device__ float g_P [(size_t)BATCH * 8 * SEQ];     // per n-tile partial row sums
__device__ float g_Ri[(size_t)BATCH * SEQ];         // 1 / rowsum

// ---------------------------------------------------------------------------
// Helpers
// ---------------------------------------------------------------------------
DEV_INLINE float to_tf32(float x) {
    unsigned u;
    asm("cvt.rna.tf32.f32 %0, %1;" : "=r"(u) : "f"(x));
    return __uint_as_float(u);
}

DEV_INLINE void mma_tf32(float c[4], const unsigned a[4], const unsigned b[2]) {
    asm volatile(
        "mma.sync.aligned.m16n8k8.row.col.f32.tf32.tf32.f32 "
        "{%0,%1,%2,%3}, {%4,%5,%6,%7}, {%8,%9}, {%0,%1,%2,%3};"
        : "+f"(c[0]), "+f"(c[1]), "+f"(c[2]), "+f"(c[3])
        : "r"(a[0]), "r"(a[1]), "r"(a[2]), "r"(a[3]), "r"(b[0]), "r"(b[1]));
}

DEV_INLINE void ldsm4(uint32_t addr, unsigned& r0, unsigned& r1,
                      unsigned& r2, unsigned& r3) {
    asm volatile("ldmatrix.sync.aligned.m8n8.x4.shared.b16 {%0,%1,%2,%3}, [%4];"
                 : "=r"(r0), "=r"(r1), "=r"(r2), "=r"(r3) : "r"(addr));
}

DEV_INLINE uint32_t smem_u32(const void* p) {
    uint32_t a;
    asm("{ .reg .u64 t; cvta.to.shared.u64 t, %1; cvt.u32.u64 %0, t; }" : "=r"(a) : "l"(p));
    return a;
}

DEV_INLINE float wsum(float v) {
    #pragma unroll
    for (int o = 16; o; o >>= 1) v += __shfl_xor_sync(0xffffffffu, v, o);
    return v;
}

// ---------------------------------------------------------------------------
// tf32 NT GEMM with ldmatrix fragment loads.
//   EPI 0: C = A@B^T + bias[col]
//   EPI 1: scores: store exp(scale*s + shift-inv mask bias), per-row partials
//   EPI 3: C = (A@B^T) * aux[row]   (1/rowsum scaling)
// 256 threads, 8 warps (4m x 2n), warp tile 32x64.
// ---------------------------------------------------------------------------
template<int EPI>
__global__ void __launch_bounds__(256) gemm_k(
    const float* __restrict__ Ag, const float* __restrict__ Bg,
    const float* __restrict__ aux, float* __restrict__ Cg,
    int Kdim, int ldA, int ldB, int ldC,
    size_t sA, size_t sB, size_t sC, int auxStride,
    float* __restrict__ Ppart)
{
    __shared__ float sA2[2][TILE_WORDS];
    __shared__ float sB2[2][TILE_WORDS];

    const int z = blockIdx.z;
    const float* A    = Ag  + (size_t)z * sA;
    const float* B    = Bg  + (size_t)z * sB;
    float*       C    = Cg  + (size_t)z * sC;
    const float* auxp = aux + (size_t)z * auxStride;

    const int m0 = blockIdx.y * BM;
    const int n0 = blockIdx.x * BN;
    const int tid  = threadIdx.x;
    const int warp = tid >> 5, lane = tid & 31;
    const int wm = warp >> 1, wn = warp & 1;
    const int gr = lane >> 2, tig = lane & 3;

    float acc[2][8][4];
    #pragma unroll
    for (int t = 0; t < 2; t++)
        #pragma unroll
        for (int j = 0; j < 8; j++)
            #pragma unroll
            for (int q = 0; q < 4; q++) acc[t][j][q] = 0.f;

    // staging indices: thread -> rows ar, ar+64; k cols ac..ac+3
    const int ar = tid >> 2;
    const int ac = (tid & 3) * 4;

    // ldmatrix per-lane source coordinates (derived fragment mapping)
    const int la_row = lane & 15;               // A: row within 16-row tile
    const int la_k   = (lane >> 4) * 4;         // A: k column base (0 or 4)
    const int lb_n   = (lane & 7) + ((lane >> 4) << 3);   // B: n within 16
    const int lb_k   = ((lane >> 3) & 1) * 4;             // B: k base (0 or 4)

    // float offsets into a tile for this lane (excluding kk term)
    const int aoff0 = (wm * 32 + la_row) * ST + la_k;
    const int aoff1 = aoff0 + 16 * ST;
    int boff[4];
    #pragma unroll
    for (int jb = 0; jb < 4; jb++)
        boff[jb] = (wn * 64 + jb * 16 + lb_n) * ST + lb_k;

    const uint32_t sAb[2] = { smem_u32(&sA2[0][0]), smem_u32(&sA2[1][0]) };
    const uint32_t sBb[2] = { smem_u32(&sB2[0][0]), smem_u32(&sB2[1][0]) };

    float4 ra[2], rb[2];
    auto gload = [&](int k0) {
        const float* ap = A + (size_t)(m0 + ar) * ldA + k0 + ac;
        ra[0] = *(const float4*)ap;
        ra[1] = *(const float4*)(ap + (size_t)64 * ldA);
        const float* bp = B + (size_t)(n0 + ar) * ldB + k0 + ac;
        rb[0] = *(const float4*)bp;
        rb[1] = *(const float4*)(bp + (size_t)64 * ldB);
    };
    auto stage = [&](int buf) {
        float4 v;
        v.x = to_tf32(ra[0].x); v.y = to_tf32(ra[0].y);
        v.z = to_tf32(ra[0].z); v.w = to_tf32(ra[0].w);
        *(float4*)&sA2[buf][ar * ST + ac] = v;
        v.x = to_tf32(ra[1].x); v.y = to_tf32(ra[1].y);
        v.z = to_tf32(ra[1].z); v.w = to_tf32(ra[1].w);
        *(float4*)&sA2[buf][(ar + 64) * ST + ac] = v;
        v.x = to_tf32(rb[0].x); v.y = to_tf32(rb[0].y);
        v.z = to_tf32(rb[0].z); v.w = to_tf32(rb[0].w);
        *(float4*)&sB2[buf][ar * ST + ac] = v;
        v.x = to_tf32(rb[1].x); v.y = to_tf32(rb[1].y);
        v.z = to_tf32(rb[1].z); v.w = to_tf32(rb[1].w);
        *(float4*)&sB2[buf][(ar + 64) * ST + ac] = v;
    };

    gload(0);
    stage(0);
    __syncthreads();

    const int KB = Kdim / BK;
    for (int kt = 0; kt < KB; kt++) {
        const int cur = kt & 1;
        const bool more = (kt + 1 < KB);
        if (more) gload((kt + 1) * BK);

        #pragma unroll
        for (int kk = 0; kk < 2; kk++) {
            unsigned af[2][4];
            ldsm4(sAb[cur] + (aoff0 + kk * 8) * 4,
                  af[0][0], af[0][1], af[0][2], af[0][3]);
            ldsm4(sAb[cur] + (aoff1 + kk * 8) * 4,
                  af[1][0], af[1][1], af[1][2], af[1][3]);
            unsigned bf[4][4];
            #pragma unroll
            for (int jb = 0; jb < 4; jb++)
                ldsm4(sBb[cur] + (boff[jb] + kk * 8) * 4,
                      bf[jb][0], bf[jb][1], bf[jb][2], bf[jb][3]);
            #pragma unroll
            for (int j = 0; j < 8; j++) {
                const unsigned* bp = &bf[j >> 1][(j & 1) * 2];
                mma_tf32(acc[0][j], af[0], bp);
                mma_tf32(acc[1][j], af[1], bp);
            }
        }

        if (more) stage(cur ^ 1);
        __syncthreads();
    }

    // Epilogue
    const float SCALE = 0.0625f;  // 1/sqrt(256)
    float rs[2][2];
    rs[0][0] = rs[0][1] = rs[1][0] = rs[1][1] = 0.f;

    #pragma unroll
    for (int t = 0; t < 2; t++) {
        const int r0 = m0 + wm * 32 + t * 16 + gr;
        const int r1 = r0 + 8;
        float mq0 = 0.f, mq1 = 0.f, rv0 = 0.f, rv1 = 0.f;
        if (EPI == 1) { mq0 = auxp[r0]; mq1 = auxp[r1]; }
        if (EPI == 3) { rv0 = auxp[r0]; rv1 = auxp[r1]; }
        #pragma unroll
        for (int j = 0; j < 8; j++) {
            const int c = n0 + wn * 64 + j * 8 + 2 * tig;
            float x0 = acc[t][j][0], x1 = acc[t][j][1];
            float x2 = acc[t][j][2], x3 = acc[t][j][3];
            if (EPI == 0) {
                const float b0 = auxp[c], b1 = auxp[c + 1];
                float2 v0 = {x0 + b0, x1 + b1};
                float2 v1 = {x2 + b0, x3 + b1};
                *(float2*)&C[(size_t)r0 * ldC + c] = v0;
                *(float2*)&C[(size_t)r1 * ldC + c] = v1;
            } else if (EPI == 1) {
                // shift-invariant mask bias: mq ? (mk ? +1 : masked->0) : 0
                const float mc0 = auxp[c], mc1 = auxp[c + 1];
                float e00, e01, e10, e11;
                if (mq0 > 0.5f) {
                    e00 = (mc0 > 0.5f) ? __expf(x0 * SCALE + 1.f) : 0.f;
                    e01 = (mc1 > 0.5f) ? __expf(x1 * SCALE + 1.f) : 0.f;
                } else {
                    e00 = __expf(x0 * SCALE);
                    e01 = __expf(x1 * SCALE);
                }
                if (mq1 > 0.5f) {
                    e10 = (mc0 > 0.5f) ? __expf(x2 * SCALE + 1.f) : 0.f;
                    e11 = (mc1 > 0.5f) ? __expf(x3 * SCALE + 1.f) : 0.f;
                } else {
                    e10 = __expf(x2 * SCALE);
                    e11 = __expf(x3 * SCALE);
                }
                rs[t][0] += e00 + e01;
                rs[t][1] += e10 + e11;
                float2 v0 = {e00, e01};
                float2 v1 = {e10, e11};
                *(float2*)&C[(size_t)r0 * ldC + c] = v0;
                *(float2*)&C[(size_t)r1 * ldC + c] = v1;
            } else {
                float2 v0 = {x0 * rv0, x1 * rv0};
                float2 v1 = {x2 * rv1, x3 * rv1};
                *(float2*)&C[(size_t)r0 * ldC + c] = v0;
                *(float2*)&C[(size_t)r1 * ldC + c] = v1;
            }
        }
    }

    if (EPI == 1) {
        __syncthreads();   // all fragment reads of sA2 done before reuse
        float* part = &sA2[0][0];
        #pragma unroll
        for (int t = 0; t < 2; t++) {
            #pragma unroll
            for (int rr = 0; rr < 2; rr++) {
                float v = rs[t][rr];
                v += __shfl_xor_sync(0xffffffffu, v, 1);
                v += __shfl_xor_sync(0xffffffffu, v, 2);
                if (tig == 0)
                    part[wn * 128 + wm * 32 + t * 16 + rr * 8 + gr] = v;
            }
        }
        __syncthreads();
        if (tid < 128) {
            const float l = part[tid] + part[128 + tid];
            Ppart[((size_t)z * 8 + blockIdx.x) * SEQ + m0 + tid] = l;
        }
    }
}

// ---------------------------------------------------------------------------
// Per-batch transpose: X[z*SEQ+n][h] -> Y[z][h][n]
// ---------------------------------------------------------------------------
__global__ void __launch_bounds__(256) transpose_k(const float* __restrict__ X,
                                                  float* __restrict__ Y)
{
    __shared__ float t[32][33];
    const int z = blockIdx.z, n0 = blockIdx.x * 32, h0 = blockIdx.y * 32;
    const int tx = threadIdx.x & 31, ty = threadIdx.x >> 5;
    #pragma unroll
    for (int i = 0; i < 4; i++) {
        const int rr = ty + 8 * i;
        t[rr][tx] = X[((size_t)z * SEQ + n0 + rr) * HD + h0 + tx];
    }
    __syncthreads();
    #pragma unroll
    for (int i = 0; i < 4; i++) {
        const int rr = ty + 8 * i;
        Y[((size_t)z * HD + h0 + rr) * SEQ + n0 + tx] = t[tx][rr];
    }
}

// ---------------------------------------------------------------------------
// Combine per-tile partial sums into 1/rowsum
// ---------------------------------------------------------------------------
__global__ void __launch_bounds__(256) rinv_k(const float* __restrict__ P,
                                             float* __restrict__ R)
{
    const int i = blockIdx.x * 256 + threadIdx.x;
    const int z = i >> 10, row = i & 1023;
    float l = 0.f;
    #pragma unroll
    for (int nt = 0; nt < 8; nt++)
        l += P[(((size_t)z * 8 + nt) << 10) + row];
    R[i] = 1.f / l;
}

// ---------------------------------------------------------------------------
// Y = relu(LN(X)) rowwise over H=256. One warp per row.
// ---------------------------------------------------------------------------
__global__ void __launch_bounds__(256) relu_ln_k(
    const float* __restrict__ X, const float* __restrict__ G,
    const float* __restrict__ Bt, float* __restrict__ Y)
{
    const int row  = blockIdx.x * 8 + (threadIdx.x >> 5);
    const int lane = threadIdx.x & 31;
    const float4* x4 = reinterpret_cast<const float4*>(X + (size_t)row * HD);
    float4 a = x4[lane], b = x4[lane + 32];

    float s = a.x + a.y + a.z + a.w + b.x + b.y + b.z + b.w;
    s = wsum(s);
    const float mu = s * (1.f / HD);
    a.x -= mu; a.y -= mu; a.z -= mu; a.w -= mu;
    b.x -= mu; b.y -= mu; b.z -= mu; b.w -= mu;
    float q = a.x*a.x + a.y*a.y + a.z*a.z + a.w*a.w
            + b.x*b.x + b.y*b.y + b.z*b.z + b.w*b.w;
    q = wsum(q);
    const float inv = rsqrtf(q * (1.f / HD) + 1e-5f);

    const float4* g4 = reinterpret_cast<const float4*>(G);
    const float4* c4 = reinterpret_cast<const float4*>(Bt);
    float4 g0 = g4[lane], g1 = g4[lane + 32];
    float4 c0 = c4[lane], c1 = c4[lane + 32];

    float4 o0, o1;
    o0.x = fmaxf(a.x * inv * g0.x + c0.x, 0.f);
    o0.y = fmaxf(a.y * inv * g0.y + c0.y, 0.f);
    o0.z = fmaxf(a.z * inv * g0.z + c0.z, 0.f);
    o0.w = fmaxf(a.w * inv * g0.w + c0.w, 0.f);
    o1.x = fmaxf(b.x * inv * g1.x + c1.x, 0.f);
    o1.y = fmaxf(b.y * inv * g1.y + c1.y, 0.f);
    o1.z = fmaxf(b.z * inv * g1.z + c1.z, 0.f);
    o1.w = fmaxf(b.w * inv * g1.w + c1.w, 0.f);

    float4* y4 = reinterpret_cast<float4*>(Y + (size_t)row * HD);
    y4[lane] = o0; y4[lane + 32] = o1;
}

// ---------------------------------------------------------------------------
// Y = LN(Xa) + LN(Xb), optional relu. One warp per row.
// ---------------------------------------------------------------------------
__global__ void __launch_bounds__(256) dual_ln_add_k(
    const float* __restrict__ Xa, const float* __restrict__ Xb,
    const float* __restrict__ Ga, const float* __restrict__ Ba,
    const float* __restrict__ Gb, const float* __restrict__ Bb,
    float* __restrict__ Y, int doRelu)
{
    const int row  = blockIdx.x * 8 + (threadIdx.x >> 5);
    const int lane = threadIdx.x & 31;

    const float4* xa4 = reinterpret_cast<const float4*>(Xa + (size_t)row * HD);
    const float4* xb4 = reinterpret_cast<const float4*>(Xb + (size_t)row * HD);
    float4 a0 = xa4[lane], a1 = xa4[lane + 32];
    float4 b0 = xb4[lane], b1 = xb4[lane + 32];

    float sa = a0.x+a0.y+a0.z+a0.w + a1.x+a1.y+a1.z+a1.w;
    float sb = b0.x+b0.y+b0.z+b0.w + b1.x+b1.y+b1.z+b1.w;
    sa = wsum(sa); sb = wsum(sb);
    const float mua = sa * (1.f / HD), mub = sb * (1.f / HD);
    a0.x-=mua; a0.y-=mua; a0.z-=mua; a0.w-=mua;
    a1.x-=mua; a1.y-=mua; a1.z-=mua; a1.w-=mua;
    b0.x-=mub; b0.y-=mub; b0.z-=mub; b0.w-=mub;
    b1.x-=mub; b1.y-=mub; b1.z-=mub; b1.w-=mub;
    float qa = a0.x*a0.x+a0.y*a0.y+a0.z*a0.z+a0.w*a0.w
             + a1.x*a1.x+a1.y*a1.y+a1.z*a1.z+a1.w*a1.w;
    float qb = b0.x*b0.x+b0.y*b0.y+b0.z*b0.z+b0.w*b0.w
             + b1.x*b1.x+b1.y*b1.y+b1.z*b1.z+b1.w*b1.w;
    qa = wsum(qa); qb = wsum(qb);
    const float inva = rsqrtf(qa * (1.f / HD) + 1e-5f);
    const float invb = rsqrtf(qb * (1.f / HD) + 1e-5f);

    const float4* ga4 = reinterpret_cast<const float4*>(Ga);
    const float4* ba4 = reinterpret_cast<const float4*>(Ba);
    const float4* gb4 = reinterpret_cast<const float4*>(Gb);
    const float4* bb4 = reinterpret_cast<const float4*>(Bb);
    float4 ga0 = ga4[lane], ga1 = ga4[lane + 32];
    float4 ca0 = ba4[lane], ca1 = ba4[lane + 32];
    float4 gb0 = gb4[lane], gb1 = gb4[lane + 32];
    float4 cb0 = bb4[lane], cb1 = bb4[lane + 32];

    float4 o0, o1;
    o0.x = (a0.x*inva*ga0.x + ca0.x) + (b0.x*invb*gb0.x + cb0.x);
    o0.y = (a0.y*inva*ga0.y + ca0.y) + (b0.y*invb*gb0.y + cb0.y);
    o0.z = (a0.z*inva*ga0.z + ca0.z) + (b0.z*invb*gb0.z + cb0.z);
    o0.w = (a0.w*inva*ga0.w + ca0.w) + (b0.w*invb*gb0.w + cb0.w);
    o1.x = (a1.x*inva*ga1.x + ca1.x) + (b1.x*invb*gb1.x + cb1.x);
    o1.y = (a1.y*inva*ga1.y + ca1.y) + (b1.y*invb*gb1.y + cb1.y);
    o1.z = (a1.z*inva*ga1.z + ca1.z) + (b1.z*invb*gb1.z + cb1.z);
    o1.w = (a1.w*inva*ga1.w + ca1.w) + (b1.w*invb*gb1.w + cb1.w);
    if (doRelu) {
        o0.x = fmaxf(o0.x, 0.f); o0.y = fmaxf(o0.y, 0.f);
        o0.z = fmaxf(o0.z, 0.f); o0.w = fmaxf(o0.w, 0.f);
        o1.x = fmaxf(o1.x, 0.f); o1.y = fmaxf(o1.y, 0.f);
        o1.z = fmaxf(o1.z, 0.f); o1.w = fmaxf(o1.w, 0.f);
    }

    float4* y4 = reinterpret_cast<float4*>(Y + (size_t)row * HD);
    y4[lane] = o0; y4[lane + 32] = o1;
}

// ---------------------------------------------------------------------------
// Host launch
// ---------------------------------------------------------------------------
extern "C" void kernel_launch(void* const* d_in, const int* in_sizes, int n_in,
                              void* d_out, int out_size)
{
    (void)in_sizes; (void)n_in; (void)out_size;
    const float* feats   = (const float*)d_in[0];
    const float* masks   = (const float*)d_in[1];
    const float* qw      = (const float*)d_in[2];
    const float* qbias   = (const float*)d_in[3];
    const float* kw      = (const float*)d_in[4];
    const float* kbias   = (const float*)d_in[5];
    const float* vw      = (const float*)d_in[6];
    const float* vbias   = (const float*)d_in[7];
    const float* alng    = (const float*)d_in[8];
    const float* alnb    = (const float*)d_in[9];
    const float* caw     = (const float*)d_in[10];
    const float* cabias  = (const float*)d_in[11];
    const float* calng   = (const float*)d_in[12];
    const float* calnb   = (const float*)d_in[13];
    const float* lw      = (const float*)d_in[14];
    const float* lbias   = (const float*)d_in[15];
    const float* llng    = (const float*)d_in[16];
    const float* llnb    = (const float*)d_in[17];
    float* out = (float*)d_out;

    float *Q, *K, *V, *VT, *O, *X1, *T1, *T2, *F, *S, *P, *Ri;
    cudaGetSymbolAddress((void**)&Q,  g_Q);
    cudaGetSymbolAddress((void**)&K,  g_K);
    cudaGetSymbolAddress((void**)&V,  g_V);
    cudaGetSymbolAddress((void**)&VT, g_VT);
    cudaGetSymbolAddress((void**)&O,  g_O);
    cudaGetSymbolAddress((void**)&X1, g_X1);
    cudaGetSymbolAddress((void**)&T1, g_T1);
    cudaGetSymbolAddress((void**)&T2, g_T2);
    cudaGetSymbolAddress((void**)&F,  g_F);
    cudaGetSymbolAddress((void**)&S,  g_S);
    cudaGetSymbolAddress((void**)&P,  g_P);
    cudaGetSymbolAddress((void**)&Ri, g_Ri);

    const dim3 blk(256);
    const dim3 gProj(HD / BN, MTOT / BM, 1);          // (2, 256)
    const dim3 gScore(SEQ / BN, SEQ / BM, BATCH);     // (8, 8, 32)
    const dim3 gPV(HD / BN, SEQ / BM, BATCH);         // (2, 8, 32)
    const dim3 gTr(SEQ / 32, HD / 32, BATCH);

    for (int i = 0; i < 3; i++) {
        const float* Fin = (i == 0) ? feats : F;
        const size_t wOff = (size_t)i * HD * HD;
        const size_t bOff = (size_t)i * HD;

        gemm_k<0><<<gProj, blk>>>(Fin, qw + wOff, qbias + bOff, Q,
                                  HD, HD, HD, HD, 0, 0, 0, 0, nullptr);
        gemm_k<0><<<gProj, blk>>>(Fin, kw + wOff, kbias + bOff, K,
                                  HD, HD, HD, HD, 0, 0, 0, 0, nullptr);
        gemm_k<0><<<gProj, blk>>>(Fin, vw + wOff, vbias + bOff, V,
                                  HD, HD, HD, HD, 0, 0, 0, 0, nullptr);

        transpose_k<<<gTr, blk>>>(V, VT);

        // scores: exp(scaled + shift-invariant mask bias), per-tile row sums
        gemm_k<1><<<gScore, blk>>>(Q, K, masks, S,
                                   HD, HD, HD, SEQ,
                                   (size_t)SEQ * HD, (size_t)SEQ * HD,
                                   (size_t)SEQ * SEQ, SEQ, P);

        rinv_k<<<MTOT / 256, blk>>>(P, Ri);

        // PV: A = S [1024 x 1024], B = V^T [256 x 1024], rows scaled by 1/rowsum
        gemm_k<3><<<gPV, blk>>>(S, VT, Ri, O,
                                SEQ, SEQ, SEQ, HD,
                                (size_t)SEQ * SEQ, (size_t)HD * SEQ,
                                (size_t)SEQ * HD, SEQ, nullptr);

        relu_ln_k<<<MTOT / 8, blk>>>(O, alng + bOff, alnb + bOff, X1);

        gemm_k<0><<<gProj, blk>>>(X1, caw + wOff, cabias + bOff, T1,
                                  HD, HD, HD, HD, 0, 0, 0, 0, nullptr);
        gemm_k<0><<<gProj, blk>>>(Fin, lw + wOff, lbias + bOff, T2,
                                  HD, HD, HD, HD, 0, 0, 0, 0, nullptr);

        dual_ln_add_k<<<MTOT / 8, blk>>>(T1, T2,
                                         calng + bOff, calnb + bOff,
                                         llng + bOff, llnb + bOff,
                                         (i == 2) ? out : F, (i < 2) ? 1 : 0);
    }
}